// round 1
// baseline (speedup 1.0000x reference)
#include <cuda_runtime.h>
#include <cuda_bf16.h>
#include <math.h>
#include <stdint.h>

#define BB 64
#define TT 256
#define CC 1024
#define HH 16
#define HD 64
#define MM (BB*TT)      /* 16384 rows */
#define EPSQ 1e-5f

/* ------------------------- scratch (static device globals) ----------------- */
__device__ float          g_wmean[4];
__device__ double         g_partial[4*256];
__device__ __nv_bfloat16  g_wq[4][CC*CC];
__device__ __nv_bfloat16  g_xq[MM*CC];
__device__ float          g_ascale[MM];
__device__ float          g_qb[MM*CC];
__device__ float          g_kb[MM*CC];
__device__ float          g_vb[MM*CC];
__device__ float          g_yb[MM*CC];
__device__ __nv_bfloat16  g_yq[MM*CC];
__device__ float          g_yscale[MM];

/* ------------------------- weight abs-mean reduction ----------------------- */
__global__ void k_abs_partial(const float* __restrict__ w, double* __restrict__ part)
{
    __shared__ double sm[256];
    const int n4 = CC*CC/4;
    double s = 0.0;
    const float4* w4 = (const float4*)w;
    for (int i = blockIdx.x*256 + threadIdx.x; i < n4; i += 256*256) {
        float4 v = w4[i];
        s += (double)fabsf(v.x) + (double)fabsf(v.y) + (double)fabsf(v.z) + (double)fabsf(v.w);
    }
    sm[threadIdx.x] = s; __syncthreads();
    for (int o = 128; o > 0; o >>= 1) {
        if (threadIdx.x < o) sm[threadIdx.x] += sm[threadIdx.x + o];
        __syncthreads();
    }
    if (threadIdx.x == 0) part[blockIdx.x] = sm[0];
}

__global__ void k_finalize_mean(const double* __restrict__ part, float* __restrict__ out)
{
    __shared__ double sm[256];
    sm[threadIdx.x] = part[threadIdx.x]; __syncthreads();
    for (int o = 128; o > 0; o >>= 1) {
        if (threadIdx.x < o) sm[threadIdx.x] += sm[threadIdx.x + o];
        __syncthreads();
    }
    if (threadIdx.x == 0)
        out[0] = fmaxf((float)(sm[0] / (double)(CC*CC)), EPSQ);
}

/* ------------------------- ternarize weights ------------------------------- */
__device__ __forceinline__ unsigned pack_bf2(float a, float b)
{
    __nv_bfloat162 t = __floats2bfloat162_rn(a, b);
    return *reinterpret_cast<unsigned*>(&t);
}

__global__ void k_ternarize(const float* __restrict__ w, __nv_bfloat16* __restrict__ wq,
                            const float* __restrict__ mean)
{
    float inv = 1.0f / mean[0];
    int i = blockIdx.x*blockDim.x + threadIdx.x;   /* one float4 per thread */
    float4 v = ((const float4*)w)[i];
    float t0 = fminf(fmaxf(rintf(v.x*inv), -1.f), 1.f);
    float t1 = fminf(fmaxf(rintf(v.y*inv), -1.f), 1.f);
    float t2 = fminf(fmaxf(rintf(v.z*inv), -1.f), 1.f);
    float t3 = fminf(fmaxf(rintf(v.w*inv), -1.f), 1.f);
    uint2 u; u.x = pack_bf2(t0,t1); u.y = pack_bf2(t2,t3);
    ((uint2*)wq)[i] = u;
}

/* ------------------------- per-row activation quant ------------------------ */
__global__ void k_act_quant(const float* __restrict__ x, __nv_bfloat16* __restrict__ xq,
                            float* __restrict__ ascale)
{
    int row = blockIdx.x;
    int tid = threadIdx.x;     /* 128 threads, 8 floats each */
    const float4* xr = (const float4*)(x + (size_t)row*CC);
    float4 v0 = xr[tid*2];
    float4 v1 = xr[tid*2+1];
    float m = fmaxf(fmaxf(fmaxf(fabsf(v0.x), fabsf(v0.y)), fmaxf(fabsf(v0.z), fabsf(v0.w))),
                    fmaxf(fmaxf(fabsf(v1.x), fabsf(v1.y)), fmaxf(fabsf(v1.z), fabsf(v1.w))));
    for (int o = 16; o; o >>= 1) m = fmaxf(m, __shfl_xor_sync(0xffffffffu, m, o));
    __shared__ float sm[4];
    if ((tid & 31) == 0) sm[tid >> 5] = m;
    __syncthreads();
    m = fmaxf(fmaxf(sm[0], sm[1]), fmaxf(sm[2], sm[3]));
    float cm = fmaxf(m, EPSQ);
    float s  = 127.0f / cm;
    float q0 = fminf(fmaxf(rintf(v0.x*s), -128.f), 127.f);
    float q1 = fminf(fmaxf(rintf(v0.y*s), -128.f), 127.f);
    float q2 = fminf(fmaxf(rintf(v0.z*s), -128.f), 127.f);
    float q3 = fminf(fmaxf(rintf(v0.w*s), -128.f), 127.f);
    float q4 = fminf(fmaxf(rintf(v1.x*s), -128.f), 127.f);
    float q5 = fminf(fmaxf(rintf(v1.y*s), -128.f), 127.f);
    float q6 = fminf(fmaxf(rintf(v1.z*s), -128.f), 127.f);
    float q7 = fminf(fmaxf(rintf(v1.w*s), -128.f), 127.f);
    uint4 u;
    u.x = pack_bf2(q0,q1); u.y = pack_bf2(q2,q3);
    u.z = pack_bf2(q4,q5); u.w = pack_bf2(q6,q7);
    *(uint4*)(xq + (size_t)row*CC + tid*8) = u;
    if (tid == 0) ascale[row] = cm * (1.0f/127.0f);
}

/* ------------------------- bf16 tensor-core GEMM --------------------------- */
/* y[m,n] = ascale[m]*wmean * sum_k A[m,k]*B[n,k] (+bias[n])                   */
#define GBM 128
#define GBN 128
#define GBK 32
#define GSTR 40   /* smem row stride (bf16 elems) */

__device__ __forceinline__ void mma16816(float* c, const uint32_t* a, const uint32_t* b)
{
    asm volatile(
        "mma.sync.aligned.m16n8k16.row.col.f32.bf16.bf16.f32 "
        "{%0,%1,%2,%3},{%4,%5,%6,%7},{%8,%9},{%0,%1,%2,%3};\n"
        : "+f"(c[0]), "+f"(c[1]), "+f"(c[2]), "+f"(c[3])
        : "r"(a[0]), "r"(a[1]), "r"(a[2]), "r"(a[3]), "r"(b[0]), "r"(b[1]));
}

__global__ __launch_bounds__(256) void k_gemm(
    const __nv_bfloat16* __restrict__ A, const __nv_bfloat16* __restrict__ Bw,
    float* __restrict__ Cout, const float* __restrict__ ascale,
    const float* __restrict__ wmean, const float* __restrict__ bias,
    int Mdim, int Ndim, int Kdim)
{
    __shared__ __nv_bfloat16 sA[GBM*GSTR];
    __shared__ __nv_bfloat16 sB[GBN*GSTR];
    int tid  = threadIdx.x;
    int m0   = blockIdx.y*GBM, n0 = blockIdx.x*GBN;
    int wid  = tid >> 5, lane = tid & 31;
    int wm_  = wid & 3, wn_ = wid >> 2;
    int g    = lane >> 2, t = lane & 3;
    float acc[2][8][4];
    #pragma unroll
    for (int mi=0;mi<2;mi++)
        #pragma unroll
        for (int nj=0;nj<8;nj++)
            #pragma unroll
            for (int q=0;q<4;q++) acc[mi][nj][q] = 0.f;

    for (int kt = 0; kt < Kdim; kt += GBK) {
        __syncthreads();
        {
            int c = tid;        int r = c>>2, col = (c&3)*8;
            *(uint4*)&sA[r*GSTR+col] = *(const uint4*)&A[(size_t)(m0+r)*Kdim + kt + col];
            *(uint4*)&sB[r*GSTR+col] = *(const uint4*)&Bw[(size_t)(n0+r)*Kdim + kt + col];
            c = tid + 256;      r = c>>2; col = (c&3)*8;
            *(uint4*)&sA[r*GSTR+col] = *(const uint4*)&A[(size_t)(m0+r)*Kdim + kt + col];
            *(uint4*)&sB[r*GSTR+col] = *(const uint4*)&Bw[(size_t)(n0+r)*Kdim + kt + col];
        }
        __syncthreads();
        #pragma unroll
        for (int kk = 0; kk < 2; kk++) {
            int k0 = kk*16;
            uint32_t af[2][4], bf[8][2];
            #pragma unroll
            for (int mi=0;mi<2;mi++) {
                int rb = wm_*32 + mi*16;
                af[mi][0] = *(const uint32_t*)&sA[(rb+g  )*GSTR + k0 + 2*t    ];
                af[mi][1] = *(const uint32_t*)&sA[(rb+g+8)*GSTR + k0 + 2*t    ];
                af[mi][2] = *(const uint32_t*)&sA[(rb+g  )*GSTR + k0 + 2*t + 8];
                af[mi][3] = *(const uint32_t*)&sA[(rb+g+8)*GSTR + k0 + 2*t + 8];
            }
            #pragma unroll
            for (int nj=0;nj<8;nj++) {
                int nb = wn_*64 + nj*8 + g;
                bf[nj][0] = *(const uint32_t*)&sB[nb*GSTR + k0 + 2*t    ];
                bf[nj][1] = *(const uint32_t*)&sB[nb*GSTR + k0 + 2*t + 8];
            }
            #pragma unroll
            for (int mi=0;mi<2;mi++)
                #pragma unroll
                for (int nj=0;nj<8;nj++)
                    mma16816(acc[mi][nj], af[mi], bf[nj]);
        }
    }

    float wm = wmean[0];
    #pragma unroll
    for (int mi=0;mi<2;mi++) {
        int r0 = m0 + wm_*32 + mi*16 + g;
        float sc0 = ascale[r0]  * wm;
        float sc1 = ascale[r0+8]* wm;
        #pragma unroll
        for (int nj=0;nj<8;nj++) {
            int cidx = n0 + wn_*64 + nj*8 + 2*t;
            float b0 = 0.f, b1 = 0.f;
            if (bias) { b0 = bias[cidx]; b1 = bias[cidx+1]; }
            Cout[(size_t)r0*Ndim     + cidx  ] = acc[mi][nj][0]*sc0 + b0;
            Cout[(size_t)r0*Ndim     + cidx+1] = acc[mi][nj][1]*sc0 + b1;
            Cout[(size_t)(r0+8)*Ndim + cidx  ] = acc[mi][nj][2]*sc1 + b0;
            Cout[(size_t)(r0+8)*Ndim + cidx+1] = acc[mi][nj][3]*sc1 + b1;
        }
    }
}

/* ------------------------- fp32 causal attention --------------------------- */
/* one block = (b, h, 64-query tile); full K/V (256x64) resident in smem       */
#define AST 68   /* padded stride (floats): conflict-free + float4-aligned */

__global__ __launch_bounds__(256) void k_attn(
    const float* __restrict__ Q, const float* __restrict__ K,
    const float* __restrict__ V, float* __restrict__ Y)
{
    extern __shared__ float smem[];
    float* sQ = smem;                       /*  64 x AST */
    float* sK = smem + 64*AST;              /* 256 x AST, reused for P^T     */
    float* sV = smem + 64*AST + 256*AST;    /* 256 x AST */

    int tid = threadIdx.x;
    int qt = blockIdx.x, h = blockIdx.y, b = blockIdx.z;
    size_t baseQrow = (size_t)b*TT + qt*64;
    size_t baseKrow = (size_t)b*TT;
    int colbase = h*HD;

    #pragma unroll
    for (int i=0;i<4;i++) {
        int idx = tid + i*256; int r = idx>>4, d4 = (idx&15)*4;
        *(float4*)&sQ[r*AST + d4] = *(const float4*)&Q[(baseQrow + r)*CC + colbase + d4];
    }
    #pragma unroll
    for (int i=0;i<16;i++) {
        int idx = tid + i*256; int r = idx>>4, d4 = (idx&15)*4;
        *(float4*)&sK[r*AST + d4] = *(const float4*)&K[(baseKrow + r)*CC + colbase + d4];
        *(float4*)&sV[r*AST + d4] = *(const float4*)&V[(baseKrow + r)*CC + colbase + d4];
    }
    __syncthreads();

    /* scores: warp w owns q rows w*8..w*8+7; lane owns keys lane+32j */
    int wq_ = tid >> 5;
    int lane = tid & 31;
    int q0 = wq_*8;
    float acc[8][8];
    #pragma unroll
    for (int i=0;i<8;i++)
        #pragma unroll
        for (int j=0;j<8;j++) acc[i][j] = 0.f;

    for (int d = 0; d < HD; d += 4) {
        float4 qv[8];
        #pragma unroll
        for (int i=0;i<8;i++) qv[i] = *(const float4*)&sQ[(q0+i)*AST + d];
        #pragma unroll
        for (int j=0;j<8;j++) {
            float4 kv = *(const float4*)&sK[(lane+32*j)*AST + d];
            #pragma unroll
            for (int i=0;i<8;i++)
                acc[i][j] += qv[i].x*kv.x + qv[i].y*kv.y + qv[i].z*kv.z + qv[i].w*kv.w;
        }
    }

    /* causal mask + softmax (rows live inside one warp) */
    int qgb = qt*64 + q0;
    #pragma unroll
    for (int i=0;i<8;i++) {
        int qg = qgb + i;
        float mx = -INFINITY;
        #pragma unroll
        for (int j=0;j<8;j++) {
            int kg = lane + 32*j;
            float s = acc[i][j]*0.125f;
            s = (kg <= qg) ? s : -INFINITY;
            acc[i][j] = s;
            mx = fmaxf(mx, s);
        }
        for (int o=16;o;o>>=1) mx = fmaxf(mx, __shfl_xor_sync(0xffffffffu, mx, o));
        float sum = 0.f;
        #pragma unroll
        for (int j=0;j<8;j++) { float e = expf(acc[i][j]-mx); acc[i][j] = e; sum += e; }
        for (int o=16;o;o>>=1) sum += __shfl_xor_sync(0xffffffffu, sum, o);
        float inv = 1.0f/sum;
        #pragma unroll
        for (int j=0;j<8;j++) acc[i][j] *= inv;
    }
    __syncthreads();             /* all K reads done before overwrite */

    /* P^T[k][q] overlays sK */
    #pragma unroll
    for (int j=0;j<8;j++)
        #pragma unroll
        for (int i=0;i<8;i++)
            sK[(lane+32*j)*AST + q0 + i] = acc[i][j];
    __syncthreads();

    /* y = P @ V : thread owns 4q x 4d */
    int tq2 = tid >> 4, td = tid & 15;
    int q0b = tq2*4, d0 = td*4;
    float a2[4][4];
    #pragma unroll
    for (int i=0;i<4;i++)
        #pragma unroll
        for (int j=0;j<4;j++) a2[i][j] = 0.f;
    for (int k = 0; k < TT; k++) {
        float4 pp = *(const float4*)&sK[k*AST + q0b];
        float4 vv = *(const float4*)&sV[k*AST + d0];
        float p4[4] = {pp.x, pp.y, pp.z, pp.w};
        float v4[4] = {vv.x, vv.y, vv.z, vv.w};
        #pragma unroll
        for (int i=0;i<4;i++)
            #pragma unroll
            for (int j=0;j<4;j++) a2[i][j] += p4[i]*v4[j];
    }
    #pragma unroll
    for (int i=0;i<4;i++) {
        float4 o; o.x = a2[i][0]; o.y = a2[i][1]; o.z = a2[i][2]; o.w = a2[i][3];
        *(float4*)&Y[(baseQrow + q0b + i)*CC + colbase + d0] = o;
    }
}

/* ------------------------- launch --------------------------------------- */
extern "C" void kernel_launch(void* const* d_in, const int* in_sizes, int n_in,
                              void* d_out, int out_size)
{
    const float* x  = (const float*)d_in[0];
    const float* Ws[4] = { (const float*)d_in[1], (const float*)d_in[2],
                           (const float*)d_in[3], (const float*)d_in[4] };
    const float* bp = (const float*)d_in[5];

    float* wmean;   cudaGetSymbolAddress((void**)&wmean,  g_wmean);
    double* part;   cudaGetSymbolAddress((void**)&part,   g_partial);
    __nv_bfloat16* wq; cudaGetSymbolAddress((void**)&wq,  g_wq);
    __nv_bfloat16* xq; cudaGetSymbolAddress((void**)&xq,  g_xq);
    float* ascale;  cudaGetSymbolAddress((void**)&ascale, g_ascale);
    float* qb;      cudaGetSymbolAddress((void**)&qb,     g_qb);
    float* kb;      cudaGetSymbolAddress((void**)&kb,     g_kb);
    float* vb;      cudaGetSymbolAddress((void**)&vb,     g_vb);
    float* yb;      cudaGetSymbolAddress((void**)&yb,     g_yb);
    __nv_bfloat16* yq; cudaGetSymbolAddress((void**)&yq,  g_yq);
    float* yscale;  cudaGetSymbolAddress((void**)&yscale, g_yscale);

    const int ATTN_SMEM = (64 + 256 + 256) * AST * (int)sizeof(float);  /* 156672 */
    cudaFuncSetAttribute(k_attn, cudaFuncAttributeMaxDynamicSharedMemorySize, ATTN_SMEM);

    for (int w = 0; w < 4; w++) {
        k_abs_partial  <<<256, 256>>>(Ws[w], part + w*256);
        k_finalize_mean<<<  1, 256>>>(part + w*256, wmean + w);
        k_ternarize    <<<1024,256>>>(Ws[w], wq + (size_t)w*CC*CC, wmean + w);
    }

    k_act_quant<<<MM, 128>>>(x, xq, ascale);

    dim3 ggrid(CC/GBN, MM/GBM);   /* (8, 128) */
    k_gemm<<<ggrid, 256>>>(xq, wq + 0*(size_t)CC*CC, qb, ascale, wmean+0, nullptr, MM, CC, CC);
    k_gemm<<<ggrid, 256>>>(xq, wq + 1*(size_t)CC*CC, kb, ascale, wmean+1, nullptr, MM, CC, CC);
    k_gemm<<<ggrid, 256>>>(xq, wq + 2*(size_t)CC*CC, vb, ascale, wmean+2, nullptr, MM, CC, CC);

    dim3 agrid(TT/64, HH, BB);    /* (4, 16, 64) */
    k_attn<<<agrid, 256, ATTN_SMEM>>>(qb, kb, vb, yb);

    k_act_quant<<<MM, 128>>>(yb, yq, yscale);
    k_gemm<<<ggrid, 256>>>(yq, wq + 3*(size_t)CC*CC, (float*)d_out, yscale, wmean+3, bp, MM, CC, CC);
}

// round 2
// speedup vs baseline: 1.2652x; 1.2652x over previous
#include <cuda_runtime.h>
#include <cuda_bf16.h>
#include <math.h>
#include <stdint.h>

#define BB 64
#define TT 256
#define CC 1024
#define HH 16
#define HD 64
#define MM (BB*TT)      /* 16384 rows */
#define EPSQ 1e-5f

/* ------------------------- scratch (static device globals) ----------------- */
__device__ float          g_wmean[4];
__device__ double         g_partial[4*64];
__device__ __nv_bfloat16  g_wq[4][CC*CC];
__device__ __nv_bfloat16  g_xq[MM*CC];
__device__ float          g_ascale[MM];
__device__ float          g_qb[MM*CC];
__device__ float          g_kb[MM*CC];
__device__ float          g_vb[MM*CC];
__device__ float          g_yb[MM*CC];
__device__ __nv_bfloat16  g_yq[MM*CC];
__device__ float          g_yscale[MM];

/* ------------------------- weight abs-mean reduction (all 4 fused) --------- */
__global__ void k_absmean_all(const float* __restrict__ w0, const float* __restrict__ w1,
                              const float* __restrict__ w2, const float* __restrict__ w3,
                              double* __restrict__ part)
{
    __shared__ double sm[256];
    const float* ws[4] = {w0, w1, w2, w3};
    const float4* w4 = (const float4*)ws[blockIdx.y];
    const int n4 = CC*CC/4;                 /* 262144 */
    double s = 0.0;
    for (int i = blockIdx.x*256 + threadIdx.x; i < n4; i += 64*256) {
        float4 v = w4[i];
        s += (double)fabsf(v.x) + (double)fabsf(v.y) + (double)fabsf(v.z) + (double)fabsf(v.w);
    }
    sm[threadIdx.x] = s; __syncthreads();
    for (int o = 128; o > 0; o >>= 1) {
        if (threadIdx.x < o) sm[threadIdx.x] += sm[threadIdx.x + o];
        __syncthreads();
    }
    if (threadIdx.x == 0) part[blockIdx.y*64 + blockIdx.x] = sm[0];
}

__global__ void k_finalize_all(const double* __restrict__ part, float* __restrict__ out)
{
    int w = blockIdx.x, tid = threadIdx.x;        /* 32 threads */
    double s = part[w*64 + tid] + part[w*64 + tid + 32];
    for (int o = 16; o; o >>= 1) s += __shfl_xor_sync(0xffffffffu, s, o);
    if (tid == 0) out[w] = fmaxf((float)(s / (double)(CC*CC)), EPSQ);
}

/* ------------------------- ternarize weights (all 4 fused) ----------------- */
__device__ __forceinline__ unsigned pack_bf2(float a, float b)
{
    __nv_bfloat162 t = __floats2bfloat162_rn(a, b);
    return *reinterpret_cast<unsigned*>(&t);
}

__global__ void k_ternarize_all(const float* __restrict__ w0, const float* __restrict__ w1,
                                const float* __restrict__ w2, const float* __restrict__ w3,
                                __nv_bfloat16* __restrict__ wq, const float* __restrict__ mean)
{
    const float* ws[4] = {w0, w1, w2, w3};
    int w = blockIdx.y;
    float inv = 1.0f / mean[w];
    int i = blockIdx.x*blockDim.x + threadIdx.x;   /* one float4 per thread */
    float4 v = ((const float4*)ws[w])[i];
    float t0 = fminf(fmaxf(rintf(v.x*inv), -1.f), 1.f);
    float t1 = fminf(fmaxf(rintf(v.y*inv), -1.f), 1.f);
    float t2 = fminf(fmaxf(rintf(v.z*inv), -1.f), 1.f);
    float t3 = fminf(fmaxf(rintf(v.w*inv), -1.f), 1.f);
    uint2 u; u.x = pack_bf2(t0,t1); u.y = pack_bf2(t2,t3);
    ((uint2*)(wq + (size_t)w*CC*CC))[i] = u;
}

/* ------------------------- per-row activation quant ------------------------ */
__global__ void k_act_quant(const float* __restrict__ x, __nv_bfloat16* __restrict__ xq,
                            float* __restrict__ ascale)
{
    int row = blockIdx.x;
    int tid = threadIdx.x;     /* 128 threads, 8 floats each */
    const float4* xr = (const float4*)(x + (size_t)row*CC);
    float4 v0 = xr[tid*2];
    float4 v1 = xr[tid*2+1];
    float m = fmaxf(fmaxf(fmaxf(fabsf(v0.x), fabsf(v0.y)), fmaxf(fabsf(v0.z), fabsf(v0.w))),
                    fmaxf(fmaxf(fabsf(v1.x), fabsf(v1.y)), fmaxf(fabsf(v1.z), fabsf(v1.w))));
    for (int o = 16; o; o >>= 1) m = fmaxf(m, __shfl_xor_sync(0xffffffffu, m, o));
    __shared__ float sm[4];
    if ((tid & 31) == 0) sm[tid >> 5] = m;
    __syncthreads();
    m = fmaxf(fmaxf(sm[0], sm[1]), fmaxf(sm[2], sm[3]));
    float cm = fmaxf(m, EPSQ);
    float s  = 127.0f / cm;
    float q0 = fminf(fmaxf(rintf(v0.x*s), -128.f), 127.f);
    float q1 = fminf(fmaxf(rintf(v0.y*s), -128.f), 127.f);
    float q2 = fminf(fmaxf(rintf(v0.z*s), -128.f), 127.f);
    float q3 = fminf(fmaxf(rintf(v0.w*s), -128.f), 127.f);
    float q4 = fminf(fmaxf(rintf(v1.x*s), -128.f), 127.f);
    float q5 = fminf(fmaxf(rintf(v1.y*s), -128.f), 127.f);
    float q6 = fminf(fmaxf(rintf(v1.z*s), -128.f), 127.f);
    float q7 = fminf(fmaxf(rintf(v1.w*s), -128.f), 127.f);
    uint4 u;
    u.x = pack_bf2(q0,q1); u.y = pack_bf2(q2,q3);
    u.z = pack_bf2(q4,q5); u.w = pack_bf2(q6,q7);
    *(uint4*)(xq + (size_t)row*CC + tid*8) = u;
    if (tid == 0) ascale[row] = cm * (1.0f/127.0f);
}

/* ------------------------- bf16 tensor-core GEMM --------------------------- */
/* Double-buffered cp.async, ldmatrix fragments.                               */
/* y[m,n] = ascale[m]*wmean[nblk] * sum_k A[m,k]*B[n,k] (+bias[n])             */
#define GBM 128
#define GBN 128
#define GBK 64
#define GSTR 72   /* smem row stride (bf16 elems): 64 + 8 pad */
#define STAGE_ELEMS (128*GSTR)

__device__ __forceinline__ void mma16816(float* c, const uint32_t* a, const uint32_t* b)
{
    asm volatile(
        "mma.sync.aligned.m16n8k16.row.col.f32.bf16.bf16.f32 "
        "{%0,%1,%2,%3},{%4,%5,%6,%7},{%8,%9},{%0,%1,%2,%3};\n"
        : "+f"(c[0]), "+f"(c[1]), "+f"(c[2]), "+f"(c[3])
        : "r"(a[0]), "r"(a[1]), "r"(a[2]), "r"(a[3]), "r"(b[0]), "r"(b[1]));
}

__device__ __forceinline__ void cp16(uint32_t smem_u32, const void* gmem)
{
    asm volatile("cp.async.cg.shared.global [%0], [%1], 16;\n" :: "r"(smem_u32), "l"(gmem));
}
__device__ __forceinline__ void cp_commit() { asm volatile("cp.async.commit_group;\n"); }
__device__ __forceinline__ void cp_wait0()  { asm volatile("cp.async.wait_group 0;\n"); }

__device__ __forceinline__ void ldsm4(uint32_t& r0, uint32_t& r1, uint32_t& r2, uint32_t& r3,
                                      uint32_t addr)
{
    asm volatile("ldmatrix.sync.aligned.m8n8.x4.shared.b16 {%0,%1,%2,%3},[%4];\n"
                 : "=r"(r0), "=r"(r1), "=r"(r2), "=r"(r3) : "r"(addr));
}

__global__ __launch_bounds__(256) void k_gemm(
    const __nv_bfloat16* __restrict__ A, const __nv_bfloat16* __restrict__ Bw,
    float* __restrict__ o0, float* __restrict__ o1, float* __restrict__ o2,
    const float* __restrict__ ascale, const float* __restrict__ wmean,
    const float* __restrict__ bias, int Kdim)
{
    extern __shared__ __nv_bfloat16 smem[];
    __nv_bfloat16* sA = smem;                       /* [2][128*GSTR] */
    __nv_bfloat16* sB = smem + 2*STAGE_ELEMS;       /* [2][128*GSTR] */

    const int tid  = threadIdx.x;
    const int m0   = blockIdx.y*GBM;
    const int n0g  = blockIdx.x*GBN;                /* global col across fused N */
    const int which= n0g >> 10;
    float* Cout    = (which == 0) ? o0 : (which == 1) ? o1 : o2;
    const int n0   = n0g & 1023;                    /* col within output matrix */

    const int wid  = tid >> 5, lane = tid & 31;
    const int wm_  = wid & 3, wn_ = wid >> 2;
    const int g    = lane >> 2, t = lane & 3;

    const uint32_t sAu = (uint32_t)__cvta_generic_to_shared(sA);
    const uint32_t sBu = (uint32_t)__cvta_generic_to_shared(sB);

    /* per-lane ldmatrix address offsets (elements) */
    const int aRow = lane & 15;            /* + rb */
    const int aCol = (lane >> 4) << 3;     /* + k0 */
    const int bRow = (lane & 7) + ((lane & 16) ? 8 : 0);   /* + nb0 */
    const int bCol = (lane & 8) ? 8 : 0;                   /* + k0 */

    /* cp.async per-thread chunk coords */
    const int ldR = tid >> 3;              /* 0..31 then +32 per round */
    const int ldC = (tid & 7) * 8;

    float acc[2][8][4];
    #pragma unroll
    for (int mi=0;mi<2;mi++)
        #pragma unroll
        for (int nj=0;nj<8;nj++)
            #pragma unroll
            for (int q=0;q<4;q++) acc[mi][nj][q] = 0.f;

    /* prefetch tile 0 */
    {
        #pragma unroll
        for (int i=0;i<4;i++) {
            int r = ldR + i*32;
            cp16(sAu + (uint32_t)((r*GSTR + ldC)*2),
                 A  + (size_t)(m0 + r)*Kdim + ldC);
            cp16(sBu + (uint32_t)((r*GSTR + ldC)*2),
                 Bw + (size_t)(n0g + r)*Kdim + ldC);
        }
        cp_commit();
    }

    const int NT = Kdim / GBK;     /* 16 */
    for (int kt = 0; kt < NT; kt++) {
        cp_wait0();
        __syncthreads();
        const int s  = kt & 1;
        const int sn = s ^ 1;
        if (kt + 1 < NT) {
            int kb = (kt+1)*GBK;
            #pragma unroll
            for (int i=0;i<4;i++) {
                int r = ldR + i*32;
                cp16(sAu + (uint32_t)((sn*STAGE_ELEMS + r*GSTR + ldC)*2),
                     A  + (size_t)(m0 + r)*Kdim + kb + ldC);
                cp16(sBu + (uint32_t)((sn*STAGE_ELEMS + r*GSTR + ldC)*2),
                     Bw + (size_t)(n0g + r)*Kdim + kb + ldC);
            }
            cp_commit();
        }
        const uint32_t aBase = sAu + (uint32_t)(s*STAGE_ELEMS*2);
        const uint32_t bBase = sBu + (uint32_t)(s*STAGE_ELEMS*2);
        #pragma unroll
        for (int kk = 0; kk < 4; kk++) {
            const int k0 = kk*16;
            uint32_t af[2][4], bf[8][2];
            #pragma unroll
            for (int mi=0;mi<2;mi++) {
                int rb = wm_*32 + mi*16;
                ldsm4(af[mi][0], af[mi][1], af[mi][2], af[mi][3],
                      aBase + (uint32_t)((((rb + aRow)*GSTR) + k0 + aCol)*2));
            }
            #pragma unroll
            for (int p=0;p<4;p++) {
                int nb0 = wn_*64 + p*16;
                uint32_t r0,r1,r2,r3;
                ldsm4(r0, r1, r2, r3,
                      bBase + (uint32_t)((((nb0 + bRow)*GSTR) + k0 + bCol)*2));
                bf[2*p][0] = r0; bf[2*p][1] = r1;
                bf[2*p+1][0] = r2; bf[2*p+1][1] = r3;
            }
            #pragma unroll
            for (int mi=0;mi<2;mi++)
                #pragma unroll
                for (int nj=0;nj<8;nj++)
                    mma16816(acc[mi][nj], af[mi], bf[nj]);
        }
        __syncthreads();
    }

    const float wm = wmean[which];
    #pragma unroll
    for (int mi=0;mi<2;mi++) {
        int r0 = m0 + wm_*32 + mi*16 + g;
        float sc0 = ascale[r0]  * wm;
        float sc1 = ascale[r0+8]* wm;
        #pragma unroll
        for (int nj=0;nj<8;nj++) {
            int cidx = n0 + wn_*64 + nj*8 + 2*t;
            float b0 = 0.f, b1 = 0.f;
            if (bias) { b0 = bias[cidx]; b1 = bias[cidx+1]; }
            Cout[(size_t)r0*CC     + cidx  ] = acc[mi][nj][0]*sc0 + b0;
            Cout[(size_t)r0*CC     + cidx+1] = acc[mi][nj][1]*sc0 + b1;
            Cout[(size_t)(r0+8)*CC + cidx  ] = acc[mi][nj][2]*sc1 + b0;
            Cout[(size_t)(r0+8)*CC + cidx+1] = acc[mi][nj][3]*sc1 + b1;
        }
    }
}

/* ------------------------- fp32 causal attention --------------------------- */
/* one block = (b, h, 64-query tile); full K/V (256x64) resident in smem       */
#define AST 68   /* padded stride (floats): conflict-free + float4-aligned */

__global__ __launch_bounds__(256) void k_attn(
    const float* __restrict__ Q, const float* __restrict__ K,
    const float* __restrict__ V, float* __restrict__ Y)
{
    extern __shared__ float fsmem[];
    float* sQ = fsmem;                       /*  64 x AST */
    float* sK = fsmem + 64*AST;              /* 256 x AST, reused for P^T     */
    float* sV = fsmem + 64*AST + 256*AST;    /* 256 x AST */

    int tid = threadIdx.x;
    int qt = blockIdx.x, h = blockIdx.y, b = blockIdx.z;
    size_t baseQrow = (size_t)b*TT + qt*64;
    size_t baseKrow = (size_t)b*TT;
    int colbase = h*HD;

    #pragma unroll
    for (int i=0;i<4;i++) {
        int idx = tid + i*256; int r = idx>>4, d4 = (idx&15)*4;
        *(float4*)&sQ[r*AST + d4] = *(const float4*)&Q[(baseQrow + r)*CC + colbase + d4];
    }
    #pragma unroll
    for (int i=0;i<16;i++) {
        int idx = tid + i*256; int r = idx>>4, d4 = (idx&15)*4;
        *(float4*)&sK[r*AST + d4] = *(const float4*)&K[(baseKrow + r)*CC + colbase + d4];
        *(float4*)&sV[r*AST + d4] = *(const float4*)&V[(baseKrow + r)*CC + colbase + d4];
    }
    __syncthreads();

    /* scores: warp w owns q rows w*8..w*8+7; lane owns keys lane+32j */
    int wq_ = tid >> 5;
    int lane = tid & 31;
    int q0 = wq_*8;
    float acc[8][8];
    #pragma unroll
    for (int i=0;i<8;i++)
        #pragma unroll
        for (int j=0;j<8;j++) acc[i][j] = 0.f;

    for (int d = 0; d < HD; d += 4) {
        float4 qv[8];
        #pragma unroll
        for (int i=0;i<8;i++) qv[i] = *(const float4*)&sQ[(q0+i)*AST + d];
        #pragma unroll
        for (int j=0;j<8;j++) {
            float4 kv = *(const float4*)&sK[(lane+32*j)*AST + d];
            #pragma unroll
            for (int i=0;i<8;i++)
                acc[i][j] += qv[i].x*kv.x + qv[i].y*kv.y + qv[i].z*kv.z + qv[i].w*kv.w;
        }
    }

    /* causal mask + softmax (rows live inside one warp) */
    int qgb = qt*64 + q0;
    #pragma unroll
    for (int i=0;i<8;i++) {
        int qg = qgb + i;
        float mx = -INFINITY;
        #pragma unroll
        for (int j=0;j<8;j++) {
            int kg = lane + 32*j;
            float s = acc[i][j]*0.125f;
            s = (kg <= qg) ? s : -INFINITY;
            acc[i][j] = s;
            mx = fmaxf(mx, s);
        }
        for (int o=16;o;o>>=1) mx = fmaxf(mx, __shfl_xor_sync(0xffffffffu, mx, o));
        float sum = 0.f;
        #pragma unroll
        for (int j=0;j<8;j++) { float e = expf(acc[i][j]-mx); acc[i][j] = e; sum += e; }
        for (int o=16;o;o>>=1) sum += __shfl_xor_sync(0xffffffffu, sum, o);
        float inv = 1.0f/sum;
        #pragma unroll
        for (int j=0;j<8;j++) acc[i][j] *= inv;
    }
    __syncthreads();             /* all K reads done before overwrite */

    /* P^T[k][q] overlays sK */
    #pragma unroll
    for (int j=0;j<8;j++)
        #pragma unroll
        for (int i=0;i<8;i++)
            sK[(lane+32*j)*AST + q0 + i] = acc[i][j];
    __syncthreads();

    /* y = P @ V : thread owns 4q x 4d */
    int tq2 = tid >> 4, td = tid & 15;
    int q0b = tq2*4, d0 = td*4;
    float a2[4][4];
    #pragma unroll
    for (int i=0;i<4;i++)
        #pragma unroll
        for (int j=0;j<4;j++) a2[i][j] = 0.f;
    for (int k = 0; k < TT; k++) {
        float4 pp = *(const float4*)&sK[k*AST + q0b];
        float4 vv = *(const float4*)&sV[k*AST + d0];
        float p4[4] = {pp.x, pp.y, pp.z, pp.w};
        float v4[4] = {vv.x, vv.y, vv.z, vv.w};
        #pragma unroll
        for (int i=0;i<4;i++)
            #pragma unroll
            for (int j=0;j<4;j++) a2[i][j] += p4[i]*v4[j];
    }
    #pragma unroll
    for (int i=0;i<4;i++) {
        float4 o; o.x = a2[i][0]; o.y = a2[i][1]; o.z = a2[i][2]; o.w = a2[i][3];
        *(float4*)&Y[(baseQrow + q0b + i)*CC + colbase + d0] = o;
    }
}

/* ------------------------- launch --------------------------------------- */
extern "C" void kernel_launch(void* const* d_in, const int* in_sizes, int n_in,
                              void* d_out, int out_size)
{
    const float* x  = (const float*)d_in[0];
    const float* W0 = (const float*)d_in[1];
    const float* W1 = (const float*)d_in[2];
    const float* W2 = (const float*)d_in[3];
    const float* W3 = (const float*)d_in[4];
    const float* bp = (const float*)d_in[5];

    float* wmean;   cudaGetSymbolAddress((void**)&wmean,  g_wmean);
    double* part;   cudaGetSymbolAddress((void**)&part,   g_partial);
    __nv_bfloat16* wq; cudaGetSymbolAddress((void**)&wq,  g_wq);
    __nv_bfloat16* xq; cudaGetSymbolAddress((void**)&xq,  g_xq);
    float* ascale;  cudaGetSymbolAddress((void**)&ascale, g_ascale);
    float* qb;      cudaGetSymbolAddress((void**)&qb,     g_qb);
    float* kb;      cudaGetSymbolAddress((void**)&kb,     g_kb);
    float* vb;      cudaGetSymbolAddress((void**)&vb,     g_vb);
    float* yb;      cudaGetSymbolAddress((void**)&yb,     g_yb);
    __nv_bfloat16* yq; cudaGetSymbolAddress((void**)&yq,  g_yq);
    float* yscale;  cudaGetSymbolAddress((void**)&yscale, g_yscale);

    const int GEMM_SMEM = 4*STAGE_ELEMS*(int)sizeof(__nv_bfloat16);       /* 73728  */
    const int ATTN_SMEM = (64 + 256 + 256) * AST * (int)sizeof(float);    /* 156672 */
    cudaFuncSetAttribute(k_gemm, cudaFuncAttributeMaxDynamicSharedMemorySize, GEMM_SMEM);
    cudaFuncSetAttribute(k_attn, cudaFuncAttributeMaxDynamicSharedMemorySize, ATTN_SMEM);

    /* weight prep: 3 launches total */
    k_absmean_all  <<<dim3(64,4), 256>>>(W0, W1, W2, W3, part);
    k_finalize_all <<<4, 32>>>(part, wmean);
    k_ternarize_all<<<dim3(1024,4), 256>>>(W0, W1, W2, W3, wq, wmean);

    k_act_quant<<<MM, 128>>>(x, xq, ascale);

    /* fused QKV GEMM: N = 3072 */
    dim3 gqkv(3*CC/GBN, MM/GBM);   /* (24, 128) */
    k_gemm<<<gqkv, 256, GEMM_SMEM>>>(xq, wq, qb, kb, vb, ascale, wmean, nullptr, CC);

    dim3 agrid(TT/64, HH, BB);     /* (4, 16, 64) */
    k_attn<<<agrid, 256, ATTN_SMEM>>>(qb, kb, vb, yb);

    k_act_quant<<<MM, 128>>>(yb, yq, yscale);

    /* projection GEMM: N = 1024 */
    dim3 gproj(CC/GBN, MM/GBM);    /* (8, 128) */
    float* ob = (float*)d_out;
    k_gemm<<<gproj, 256, GEMM_SMEM>>>(yq, wq + 3*(size_t)CC*CC, ob, ob, ob,
                                      yscale, wmean + 3, bp, CC);
}

// round 4
// speedup vs baseline: 1.6260x; 1.2852x over previous
#include <cuda_runtime.h>
#include <cuda_bf16.h>
#include <math.h>
#include <stdint.h>

#define BB 64
#define TT 256
#define CC 1024
#define HH 16
#define HD 64
#define MM (BB*TT)      /* 16384 rows */
#define EPSQ 1e-5f

/* ------------------------- scratch (static device globals) ----------------- */
__device__ float          g_wmean[4];
__device__ double         g_partial[4*64];
__device__ __nv_bfloat16  g_wq[4][CC*CC];
__device__ __nv_bfloat16  g_xq[MM*CC];
__device__ float          g_ascale[MM];
__device__ float          g_qb[MM*CC];
__device__ float          g_kb[MM*CC];
__device__ float          g_vb[MM*CC];
__device__ float          g_yb[MM*CC];
__device__ __nv_bfloat16  g_yq[MM*CC];
__device__ float          g_yscale[MM];

/* ------------------------- weight abs-mean reduction (all 4 fused) --------- */
__global__ void k_absmean_all(const float* __restrict__ w0, const float* __restrict__ w1,
                              const float* __restrict__ w2, const float* __restrict__ w3,
                              double* __restrict__ part)
{
    __shared__ double sm[256];
    const float* ws[4] = {w0, w1, w2, w3};
    const float4* w4 = (const float4*)ws[blockIdx.y];
    const int n4 = CC*CC/4;
    double s = 0.0;
    for (int i = blockIdx.x*256 + threadIdx.x; i < n4; i += 64*256) {
        float4 v = w4[i];
        s += (double)fabsf(v.x) + (double)fabsf(v.y) + (double)fabsf(v.z) + (double)fabsf(v.w);
    }
    sm[threadIdx.x] = s; __syncthreads();
    for (int o = 128; o > 0; o >>= 1) {
        if (threadIdx.x < o) sm[threadIdx.x] += sm[threadIdx.x + o];
        __syncthreads();
    }
    if (threadIdx.x == 0) part[blockIdx.y*64 + blockIdx.x] = sm[0];
}

__global__ void k_finalize_all(const double* __restrict__ part, float* __restrict__ out)
{
    int w = blockIdx.x, tid = threadIdx.x;
    double s = part[w*64 + tid] + part[w*64 + tid + 32];
    for (int o = 16; o; o >>= 1) s += __shfl_xor_sync(0xffffffffu, s, o);
    if (tid == 0) out[w] = fmaxf((float)(s / (double)(CC*CC)), EPSQ);
}

/* ------------------------- ternarize weights (all 4 fused) ----------------- */
__device__ __forceinline__ unsigned pack_bf2(float a, float b)
{
    __nv_bfloat162 t = __floats2bfloat162_rn(a, b);
    return *reinterpret_cast<unsigned*>(&t);
}

__global__ void k_ternarize_all(const float* __restrict__ w0, const float* __restrict__ w1,
                                const float* __restrict__ w2, const float* __restrict__ w3,
                                __nv_bfloat16* __restrict__ wq, const float* __restrict__ mean)
{
    const float* ws[4] = {w0, w1, w2, w3};
    int w = blockIdx.y;
    float inv = 1.0f / mean[w];
    int i = blockIdx.x*blockDim.x + threadIdx.x;
    float4 v = ((const float4*)ws[w])[i];
    float t0 = fminf(fmaxf(rintf(v.x*inv), -1.f), 1.f);
    float t1 = fminf(fmaxf(rintf(v.y*inv), -1.f), 1.f);
    float t2 = fminf(fmaxf(rintf(v.z*inv), -1.f), 1.f);
    float t3 = fminf(fmaxf(rintf(v.w*inv), -1.f), 1.f);
    uint2 u; u.x = pack_bf2(t0,t1); u.y = pack_bf2(t2,t3);
    ((uint2*)(wq + (size_t)w*CC*CC))[i] = u;
}

/* ------------------------- per-row activation quant ------------------------ */
__global__ void k_act_quant(const float* __restrict__ x, __nv_bfloat16* __restrict__ xq,
                            float* __restrict__ ascale)
{
    int row = blockIdx.x;
    int tid = threadIdx.x;
    const float4* xr = (const float4*)(x + (size_t)row*CC);
    float4 v0 = xr[tid*2];
    float4 v1 = xr[tid*2+1];
    float m = fmaxf(fmaxf(fmaxf(fabsf(v0.x), fabsf(v0.y)), fmaxf(fabsf(v0.z), fabsf(v0.w))),
                    fmaxf(fmaxf(fabsf(v1.x), fabsf(v1.y)), fmaxf(fabsf(v1.z), fabsf(v1.w))));
    for (int o = 16; o; o >>= 1) m = fmaxf(m, __shfl_xor_sync(0xffffffffu, m, o));
    __shared__ float sm[4];
    if ((tid & 31) == 0) sm[tid >> 5] = m;
    __syncthreads();
    m = fmaxf(fmaxf(sm[0], sm[1]), fmaxf(sm[2], sm[3]));
    float cm = fmaxf(m, EPSQ);
    float s  = 127.0f / cm;
    float q0 = fminf(fmaxf(rintf(v0.x*s), -128.f), 127.f);
    float q1 = fminf(fmaxf(rintf(v0.y*s), -128.f), 127.f);
    float q2 = fminf(fmaxf(rintf(v0.z*s), -128.f), 127.f);
    float q3 = fminf(fmaxf(rintf(v0.w*s), -128.f), 127.f);
    float q4 = fminf(fmaxf(rintf(v1.x*s), -128.f), 127.f);
    float q5 = fminf(fmaxf(rintf(v1.y*s), -128.f), 127.f);
    float q6 = fminf(fmaxf(rintf(v1.z*s), -128.f), 127.f);
    float q7 = fminf(fmaxf(rintf(v1.w*s), -128.f), 127.f);
    uint4 u;
    u.x = pack_bf2(q0,q1); u.y = pack_bf2(q2,q3);
    u.z = pack_bf2(q4,q5); u.w = pack_bf2(q6,q7);
    *(uint4*)(xq + (size_t)row*CC + tid*8) = u;
    if (tid == 0) ascale[row] = cm * (1.0f/127.0f);
}

/* ------------------------- bf16 tensor-core GEMM --------------------------- */
#define GBM 128
#define GBN 128
#define GBK 64
#define GSTR 72
#define STAGE_ELEMS (128*GSTR)

__device__ __forceinline__ void mma16816(float* c, const uint32_t* a, const uint32_t* b)
{
    asm volatile(
        "mma.sync.aligned.m16n8k16.row.col.f32.bf16.bf16.f32 "
        "{%0,%1,%2,%3},{%4,%5,%6,%7},{%8,%9},{%0,%1,%2,%3};\n"
        : "+f"(c[0]), "+f"(c[1]), "+f"(c[2]), "+f"(c[3])
        : "r"(a[0]), "r"(a[1]), "r"(a[2]), "r"(a[3]), "r"(b[0]), "r"(b[1]));
}

__device__ __forceinline__ void cp16(uint32_t smem_u32, const void* gmem)
{
    asm volatile("cp.async.cg.shared.global [%0], [%1], 16;\n" :: "r"(smem_u32), "l"(gmem));
}
__device__ __forceinline__ void cp_commit() { asm volatile("cp.async.commit_group;\n"); }

__device__ __forceinline__ void ldsm4(uint32_t& r0, uint32_t& r1, uint32_t& r2, uint32_t& r3,
                                      uint32_t addr)
{
    asm volatile("ldmatrix.sync.aligned.m8n8.x4.shared.b16 {%0,%1,%2,%3},[%4];\n"
                 : "=r"(r0), "=r"(r1), "=r"(r2), "=r"(r3) : "r"(addr));
}

__global__ __launch_bounds__(256) void k_gemm(
    const __nv_bfloat16* __restrict__ A, const __nv_bfloat16* __restrict__ Bw,
    float* __restrict__ o0, float* __restrict__ o1, float* __restrict__ o2,
    const float* __restrict__ ascale, const float* __restrict__ wmean,
    const float* __restrict__ bias, int Kdim)
{
    extern __shared__ __nv_bfloat16 smem[];
    __nv_bfloat16* sA = smem;
    __nv_bfloat16* sB = smem + 2*STAGE_ELEMS;

    const int tid  = threadIdx.x;
    const int m0   = blockIdx.y*GBM;
    const int n0g  = blockIdx.x*GBN;
    const int which= n0g >> 10;
    float* Cout    = (which == 0) ? o0 : (which == 1) ? o1 : o2;
    const int n0   = n0g & 1023;

    const int wid  = tid >> 5, lane = tid & 31;
    const int wm_  = wid & 3, wn_ = wid >> 2;
    const int g    = lane >> 2, t = lane & 3;

    const uint32_t sAu = (uint32_t)__cvta_generic_to_shared(sA);
    const uint32_t sBu = (uint32_t)__cvta_generic_to_shared(sB);

    const int aRow = lane & 15;
    const int aCol = (lane >> 4) << 3;
    const int bRow = (lane & 7) + ((lane & 16) ? 8 : 0);
    const int bCol = (lane & 8) ? 8 : 0;

    const int ldR = tid >> 3;
    const int ldC = (tid & 7) * 8;

    float acc[2][8][4];
    #pragma unroll
    for (int mi=0;mi<2;mi++)
        #pragma unroll
        for (int nj=0;nj<8;nj++)
            #pragma unroll
            for (int q=0;q<4;q++) acc[mi][nj][q] = 0.f;

    {
        #pragma unroll
        for (int i=0;i<4;i++) {
            int r = ldR + i*32;
            cp16(sAu + (uint32_t)((r*GSTR + ldC)*2),
                 A  + (size_t)(m0 + r)*Kdim + ldC);
            cp16(sBu + (uint32_t)((r*GSTR + ldC)*2),
                 Bw + (size_t)(n0g + r)*Kdim + ldC);
        }
        cp_commit();
    }

    const int NT = Kdim / GBK;
    for (int kt = 0; kt < NT; kt++) {
        asm volatile("cp.async.wait_group 0;\n");
        __syncthreads();
        const int s  = kt & 1;
        const int sn = s ^ 1;
        if (kt + 1 < NT) {
            int kb = (kt+1)*GBK;
            #pragma unroll
            for (int i=0;i<4;i++) {
                int r = ldR + i*32;
                cp16(sAu + (uint32_t)((sn*STAGE_ELEMS + r*GSTR + ldC)*2),
                     A  + (size_t)(m0 + r)*Kdim + kb + ldC);
                cp16(sBu + (uint32_t)((sn*STAGE_ELEMS + r*GSTR + ldC)*2),
                     Bw + (size_t)(n0g + r)*Kdim + kb + ldC);
            }
            cp_commit();
        }
        const uint32_t aBase = sAu + (uint32_t)(s*STAGE_ELEMS*2);
        const uint32_t bBase = sBu + (uint32_t)(s*STAGE_ELEMS*2);
        #pragma unroll
        for (int kk = 0; kk < 4; kk++) {
            const int k0 = kk*16;
            uint32_t af[2][4], bf[8][2];
            #pragma unroll
            for (int mi=0;mi<2;mi++) {
                int rb = wm_*32 + mi*16;
                ldsm4(af[mi][0], af[mi][1], af[mi][2], af[mi][3],
                      aBase + (uint32_t)((((rb + aRow)*GSTR) + k0 + aCol)*2));
            }
            #pragma unroll
            for (int p=0;p<4;p++) {
                int nb0 = wn_*64 + p*16;
                uint32_t r0,r1,r2,r3;
                ldsm4(r0, r1, r2, r3,
                      bBase + (uint32_t)((((nb0 + bRow)*GSTR) + k0 + bCol)*2));
                bf[2*p][0] = r0; bf[2*p][1] = r1;
                bf[2*p+1][0] = r2; bf[2*p+1][1] = r3;
            }
            #pragma unroll
            for (int mi=0;mi<2;mi++)
                #pragma unroll
                for (int nj=0;nj<8;nj++)
                    mma16816(acc[mi][nj], af[mi], bf[nj]);
        }
        __syncthreads();
    }

    const float wm = wmean[which];
    #pragma unroll
    for (int mi=0;mi<2;mi++) {
        int r0 = m0 + wm_*32 + mi*16 + g;
        float sc0 = ascale[r0]  * wm;
        float sc1 = ascale[r0+8]* wm;
        #pragma unroll
        for (int nj=0;nj<8;nj++) {
            int cidx = n0 + wn_*64 + nj*8 + 2*t;
            float b0 = 0.f, b1 = 0.f;
            if (bias) { b0 = bias[cidx]; b1 = bias[cidx+1]; }
            Cout[(size_t)r0*CC     + cidx  ] = acc[mi][nj][0]*sc0 + b0;
            Cout[(size_t)r0*CC     + cidx+1] = acc[mi][nj][1]*sc0 + b1;
            Cout[(size_t)(r0+8)*CC + cidx  ] = acc[mi][nj][2]*sc1 + b0;
            Cout[(size_t)(r0+8)*CC + cidx+1] = acc[mi][nj][3]*sc1 + b1;
        }
    }
}

/* ------------------------- 3xTF32 tensor-core flash attention -------------- */
/* grid (qt,h,b); 128 threads = 4 warps, warp w owns query rows w*16..w*16+15 */
/* online softmax over nchunk = qt+1 chunks of 64 keys.                       */
/* Precision: x = hi + lo (hi=tf32(x), lo=tf32(x-hi)); products accumulate    */
/* hi*hi + hi*lo + lo*hi -> ~2^-22 relative error (fp32-class).               */
#define KSTR 68
#define VSTR 72
#define PSTR 68

__device__ __forceinline__ uint32_t f2tf(float f)
{
    uint32_t r; asm("cvt.rna.tf32.f32 %0, %1;\n" : "=r"(r) : "f"(f)); return r;
}
__device__ __forceinline__ void tf_split(float v, uint32_t& hi, uint32_t& lo)
{
    hi = f2tf(v);
    lo = f2tf(v - __uint_as_float(hi));
}

__device__ __forceinline__ void mma_tf32(float* c, const uint32_t* a, const uint32_t* b)
{
    asm volatile(
        "mma.sync.aligned.m16n8k8.row.col.f32.tf32.tf32.f32 "
        "{%0,%1,%2,%3},{%4,%5,%6,%7},{%8,%9},{%0,%1,%2,%3};\n"
        : "+f"(c[0]), "+f"(c[1]), "+f"(c[2]), "+f"(c[3])
        : "r"(a[0]), "r"(a[1]), "r"(a[2]), "r"(a[3]), "r"(b[0]), "r"(b[1]));
}

__global__ __launch_bounds__(128) void k_attn_tc(
    const float* __restrict__ Q, const float* __restrict__ K,
    const float* __restrict__ V, float* __restrict__ Y)
{
    extern __shared__ float fsm[];
    float* sK = fsm;                      /* [2][64*KSTR] */
    float* sV = fsm + 2*64*KSTR;          /* [2][64*VSTR] */
    float* sQ = sV + 2*64*VSTR;           /* [64*KSTR]    */
    float* sP = sQ + 64*KSTR;             /* [64*PSTR] raw fp32 P */

    const int tid = threadIdx.x;
    const int w   = tid >> 5, lane = tid & 31;
    const int g   = lane >> 2, t = lane & 3;
    const int qt  = blockIdx.x, h = blockIdx.y, b = blockIdx.z;
    const int nchunk = qt + 1;
    const size_t qrow0 = (size_t)b*TT + qt*64;
    const size_t krow0 = (size_t)b*TT;
    const int col0 = h*HD;

    const uint32_t sKu = (uint32_t)__cvta_generic_to_shared(sK);
    const uint32_t sVu = (uint32_t)__cvta_generic_to_shared(sV);

    const int ldr = tid >> 4;             /* row 0..7, +8 per step */
    const int ldc = (tid & 15) * 4;       /* float col */

    /* prefetch chunk 0 */
    {
        #pragma unroll
        for (int i=0;i<8;i++) {
            int r = ldr + i*8;
            cp16(sKu + (uint32_t)((r*KSTR + ldc)*4),
                 K + (krow0 + r)*CC + col0 + ldc);
            cp16(sVu + (uint32_t)((r*VSTR + ldc)*4),
                 V + (krow0 + r)*CC + col0 + ldc);
        }
        cp_commit();
    }

    /* stage Q and build register-resident hi/lo tf32 A-fragments */
    #pragma unroll
    for (int i=0;i<8;i++) {
        int r = ldr + i*8;
        *(float4*)&sQ[r*KSTR + ldc] = *(const float4*)&Q[(qrow0 + r)*CC + col0 + ldc];
    }
    __syncthreads();
    uint32_t qh[8][4], ql_[8][4];
    {
        const int ra = w*16;
        #pragma unroll
        for (int kk=0;kk<8;kk++) {
            tf_split(sQ[(ra+g  )*KSTR + kk*8 + t    ], qh[kk][0], ql_[kk][0]);
            tf_split(sQ[(ra+g+8)*KSTR + kk*8 + t    ], qh[kk][1], ql_[kk][1]);
            tf_split(sQ[(ra+g  )*KSTR + kk*8 + t + 4], qh[kk][2], ql_[kk][2]);
            tf_split(sQ[(ra+g+8)*KSTR + kk*8 + t + 4], qh[kk][3], ql_[kk][3]);
        }
    }

    float oacc[8][4];
    #pragma unroll
    for (int nt=0;nt<8;nt++)
        #pragma unroll
        for (int q=0;q<4;q++) oacc[nt][q] = 0.f;
    float mg = -INFINITY, mg8 = -INFINITY, lg = 0.f, lg8 = 0.f;

    for (int kc = 0; kc < nchunk; kc++) {
        __syncthreads();            /* prev compute done before buffer overwrite */
        const int buf = kc & 1;
        if (kc + 1 < nchunk) {
            const int nb = (kc+1) & 1;
            #pragma unroll
            for (int i=0;i<8;i++) {
                int r = ldr + i*8;
                cp16(sKu + (uint32_t)((nb*64*KSTR + r*KSTR + ldc)*4),
                     K + (krow0 + (kc+1)*64 + r)*CC + col0 + ldc);
                cp16(sVu + (uint32_t)((nb*64*VSTR + r*VSTR + ldc)*4),
                     V + (krow0 + (kc+1)*64 + r)*CC + col0 + ldc);
            }
            cp_commit();
            asm volatile("cp.async.wait_group 1;\n");
        } else {
            asm volatile("cp.async.wait_group 0;\n");
        }
        __syncthreads();

        const float* cK = sK + buf*64*KSTR;
        const float* cV = sV + buf*64*VSTR;

        /* S = Q K^T * 1/8 for 16 rows x 64 keys, 3xTF32 */
        float sacc[8][4];
        #pragma unroll
        for (int nt=0;nt<8;nt++) {
            #pragma unroll
            for (int q=0;q<4;q++) sacc[nt][q] = 0.f;
            #pragma unroll
            for (int kk=0;kk<8;kk++) {
                uint32_t bh[2], bl[2];
                tf_split(cK[(nt*8+g)*KSTR + kk*8 + t    ], bh[0], bl[0]);
                tf_split(cK[(nt*8+g)*KSTR + kk*8 + t + 4], bh[1], bl[1]);
                mma_tf32(sacc[nt], qh[kk],  bh);
                mma_tf32(sacc[nt], qh[kk],  bl);
                mma_tf32(sacc[nt], ql_[kk], bh);
            }
        }

        /* scale + causal mask (diagonal chunk only) */
        const bool diag = (kc == qt);
        const int qlr  = w*16 + g;       /* local row for c0,c1 */
        const int qlr8 = qlr + 8;
        #pragma unroll
        for (int nt=0;nt<8;nt++) {
            int kl0 = nt*8 + 2*t, kl1 = kl0 + 1;
            sacc[nt][0] = (diag && kl0 > qlr ) ? -INFINITY : sacc[nt][0]*0.125f;
            sacc[nt][1] = (diag && kl1 > qlr ) ? -INFINITY : sacc[nt][1]*0.125f;
            sacc[nt][2] = (diag && kl0 > qlr8) ? -INFINITY : sacc[nt][2]*0.125f;
            sacc[nt][3] = (diag && kl1 > qlr8) ? -INFINITY : sacc[nt][3]*0.125f;
        }

        /* chunk row max over this lane, then quad butterfly */
        float cm = -INFINITY, cm8 = -INFINITY;
        #pragma unroll
        for (int nt=0;nt<8;nt++) {
            cm  = fmaxf(cm,  fmaxf(sacc[nt][0], sacc[nt][1]));
            cm8 = fmaxf(cm8, fmaxf(sacc[nt][2], sacc[nt][3]));
        }
        #pragma unroll
        for (int o=1;o<4;o<<=1) {
            cm  = fmaxf(cm,  __shfl_xor_sync(0xffffffffu, cm,  o));
            cm8 = fmaxf(cm8, __shfl_xor_sync(0xffffffffu, cm8, o));
        }
        float nm  = fmaxf(mg,  cm);
        float nm8 = fmaxf(mg8, cm8);
        float sc  = __expf(mg  - nm);
        float sc8 = __expf(mg8 - nm8);
        mg = nm; mg8 = nm8;

        /* exponentiate, row-sum, store raw P to smem */
        float rs = 0.f, rs8 = 0.f;
        const int pr = w*16 + g;
        #pragma unroll
        for (int nt=0;nt<8;nt++) {
            float e0 = __expf(sacc[nt][0] - nm);
            float e1 = __expf(sacc[nt][1] - nm);
            float e2 = __expf(sacc[nt][2] - nm8);
            float e3 = __expf(sacc[nt][3] - nm8);
            rs  += e0 + e1;  rs8 += e2 + e3;
            sP[(pr  )*PSTR + nt*8 + 2*t    ] = e0;
            sP[(pr  )*PSTR + nt*8 + 2*t + 1] = e1;
            sP[(pr+8)*PSTR + nt*8 + 2*t    ] = e2;
            sP[(pr+8)*PSTR + nt*8 + 2*t + 1] = e3;
        }
        #pragma unroll
        for (int o=1;o<4;o<<=1) {
            rs  += __shfl_xor_sync(0xffffffffu, rs,  o);
            rs8 += __shfl_xor_sync(0xffffffffu, rs8, o);
        }
        lg  = lg *sc  + rs;
        lg8 = lg8*sc8 + rs8;

        /* rescale O accumulator */
        #pragma unroll
        for (int nt=0;nt<8;nt++) {
            oacc[nt][0] *= sc;  oacc[nt][1] *= sc;
            oacc[nt][2] *= sc8; oacc[nt][3] *= sc8;
        }
        __syncwarp();   /* P visible within warp (P region is per-warp) */

        /* O += P V : 3xTF32 */
        #pragma unroll
        for (int kk=0;kk<8;kk++) {
            uint32_t ph[4], pl[4];
            tf_split(sP[(pr  )*PSTR + kk*8 + t    ], ph[0], pl[0]);
            tf_split(sP[(pr+8)*PSTR + kk*8 + t    ], ph[1], pl[1]);
            tf_split(sP[(pr  )*PSTR + kk*8 + t + 4], ph[2], pl[2]);
            tf_split(sP[(pr+8)*PSTR + kk*8 + t + 4], ph[3], pl[3]);
            #pragma unroll
            for (int nt=0;nt<8;nt++) {
                uint32_t bh[2], bl[2];
                tf_split(cV[(kk*8+t  )*VSTR + nt*8 + g], bh[0], bl[0]);
                tf_split(cV[(kk*8+t+4)*VSTR + nt*8 + g], bh[1], bl[1]);
                mma_tf32(oacc[nt], ph, bh);
                mma_tf32(oacc[nt], ph, bl);
                mma_tf32(oacc[nt], pl, bh);
            }
        }
    }

    /* normalize + write */
    float inv  = 1.0f/lg;
    float inv8 = 1.0f/lg8;
    const size_t r0 = qrow0 + w*16 + g;
    #pragma unroll
    for (int nt=0;nt<8;nt++) {
        float2 o0; o0.x = oacc[nt][0]*inv;  o0.y = oacc[nt][1]*inv;
        float2 o1; o1.x = oacc[nt][2]*inv8; o1.y = oacc[nt][3]*inv8;
        *(float2*)&Y[(r0    )*CC + col0 + nt*8 + 2*t] = o0;
        *(float2*)&Y[(r0 + 8)*CC + col0 + nt*8 + 2*t] = o1;
    }
}

/* ------------------------- launch --------------------------------------- */
extern "C" void kernel_launch(void* const* d_in, const int* in_sizes, int n_in,
                              void* d_out, int out_size)
{
    const float* x  = (const float*)d_in[0];
    const float* W0 = (const float*)d_in[1];
    const float* W1 = (const float*)d_in[2];
    const float* W2 = (const float*)d_in[3];
    const float* W3 = (const float*)d_in[4];
    const float* bp = (const float*)d_in[5];

    float* wmean;   cudaGetSymbolAddress((void**)&wmean,  g_wmean);
    double* part;   cudaGetSymbolAddress((void**)&part,   g_partial);
    __nv_bfloat16* wq; cudaGetSymbolAddress((void**)&wq,  g_wq);
    __nv_bfloat16* xq; cudaGetSymbolAddress((void**)&xq,  g_xq);
    float* ascale;  cudaGetSymbolAddress((void**)&ascale, g_ascale);
    float* qb;      cudaGetSymbolAddress((void**)&qb,     g_qb);
    float* kb;      cudaGetSymbolAddress((void**)&kb,     g_kb);
    float* vb;      cudaGetSymbolAddress((void**)&vb,     g_vb);
    float* yb;      cudaGetSymbolAddress((void**)&yb,     g_yb);
    __nv_bfloat16* yq; cudaGetSymbolAddress((void**)&yq,  g_yq);
    float* yscale;  cudaGetSymbolAddress((void**)&yscale, g_yscale);

    const int GEMM_SMEM = 4*STAGE_ELEMS*(int)sizeof(__nv_bfloat16);   /* 73728  */
    const int ATTN_SMEM = (2*64*KSTR + 2*64*VSTR + 64*KSTR + 64*PSTR)
                          * (int)sizeof(float);                        /* 106496 */
    cudaFuncSetAttribute(k_gemm,    cudaFuncAttributeMaxDynamicSharedMemorySize, GEMM_SMEM);
    cudaFuncSetAttribute(k_attn_tc, cudaFuncAttributeMaxDynamicSharedMemorySize, ATTN_SMEM);

    k_absmean_all  <<<dim3(64,4), 256>>>(W0, W1, W2, W3, part);
    k_finalize_all <<<4, 32>>>(part, wmean);
    k_ternarize_all<<<dim3(1024,4), 256>>>(W0, W1, W2, W3, wq, wmean);

    k_act_quant<<<MM, 128>>>(x, xq, ascale);

    dim3 gqkv(3*CC/GBN, MM/GBM);   /* (24, 128) */
    k_gemm<<<gqkv, 256, GEMM_SMEM>>>(xq, wq, qb, kb, vb, ascale, wmean, nullptr, CC);

    dim3 agrid(TT/64, HH, BB);     /* (4, 16, 64) */
    k_attn_tc<<<agrid, 128, ATTN_SMEM>>>(qb, kb, vb, yb);

    k_act_quant<<<MM, 128>>>(yb, yq, yscale);

    dim3 gproj(CC/GBN, MM/GBM);    /* (8, 128) */
    float* ob = (float*)d_out;
    k_gemm<<<gproj, 256, GEMM_SMEM>>>(yq, wq + 3*(size_t)CC*CC, ob, ob, ob,
                                      yscale, wmean + 3, bp, CC);
}

// round 7
// speedup vs baseline: 2.0488x; 1.2600x over previous
#include <cuda_runtime.h>
#include <cuda_bf16.h>
#include <math.h>
#include <stdint.h>

#define BB 64
#define TT 256
#define CC 1024
#define HH 16
#define HD 64
#define MM (BB*TT)      /* 16384 rows */
#define EPSQ 1e-5f

/* ------------------------- scratch (static device globals) ----------------- */
__device__ float          g_wmean[4];
__device__ double         g_partial[4*64];
__device__ __nv_bfloat16  g_wq[4][CC*CC];
__device__ __nv_bfloat16  g_xq[MM*CC];
__device__ float          g_ascale[MM];
__device__ __nv_bfloat16  g_qhi[MM*CC];
__device__ __nv_bfloat16  g_qlo[MM*CC];
__device__ __nv_bfloat16  g_khi[MM*CC];
__device__ __nv_bfloat16  g_klo[MM*CC];
__device__ __nv_bfloat16  g_vhi[MM*CC];
__device__ __nv_bfloat16  g_vlo[MM*CC];
__device__ float          g_yb[MM*CC];
__device__ __nv_bfloat16  g_yq[MM*CC];
__device__ float          g_yscale[MM];

/* ------------------------- PTX helpers ------------------------------------ */
__device__ __forceinline__ void cp16(uint32_t smem_u32, const void* gmem)
{
    asm volatile("cp.async.cg.shared.global [%0], [%1], 16;\n" :: "r"(smem_u32), "l"(gmem));
}
__device__ __forceinline__ void cp_commit() { asm volatile("cp.async.commit_group;\n"); }

__device__ __forceinline__ void ldsm4(uint32_t& r0, uint32_t& r1, uint32_t& r2, uint32_t& r3,
                                      uint32_t addr)
{
    asm volatile("ldmatrix.sync.aligned.m8n8.x4.shared.b16 {%0,%1,%2,%3},[%4];\n"
                 : "=r"(r0), "=r"(r1), "=r"(r2), "=r"(r3) : "r"(addr));
}
__device__ __forceinline__ void ldsm4t(uint32_t& r0, uint32_t& r1, uint32_t& r2, uint32_t& r3,
                                       uint32_t addr)
{
    asm volatile("ldmatrix.sync.aligned.m8n8.x4.trans.shared.b16 {%0,%1,%2,%3},[%4];\n"
                 : "=r"(r0), "=r"(r1), "=r"(r2), "=r"(r3) : "r"(addr));
}

__device__ __forceinline__ void mma16816(float* c, const uint32_t* a, const uint32_t* b)
{
    asm volatile(
        "mma.sync.aligned.m16n8k16.row.col.f32.bf16.bf16.f32 "
        "{%0,%1,%2,%3},{%4,%5,%6,%7},{%8,%9},{%0,%1,%2,%3};\n"
        : "+f"(c[0]), "+f"(c[1]), "+f"(c[2]), "+f"(c[3])
        : "r"(a[0]), "r"(a[1]), "r"(a[2]), "r"(a[3]), "r"(b[0]), "r"(b[1]));
}

__device__ __forceinline__ unsigned pack_bf2(float a, float b)
{
    __nv_bfloat162 t = __floats2bfloat162_rn(a, b);
    return *reinterpret_cast<unsigned*>(&t);
}

/* ------------------------- weight abs-mean reduction (all 4 fused) --------- */
__global__ void k_absmean_all(const float* __restrict__ w0, const float* __restrict__ w1,
                              const float* __restrict__ w2, const float* __restrict__ w3,
                              double* __restrict__ part)
{
    __shared__ double sm[256];
    const float* ws[4] = {w0, w1, w2, w3};
    const float4* w4 = (const float4*)ws[blockIdx.y];
    const int n4 = CC*CC/4;
    double s = 0.0;
    for (int i = blockIdx.x*256 + threadIdx.x; i < n4; i += 64*256) {
        float4 v = w4[i];
        s += (double)fabsf(v.x) + (double)fabsf(v.y) + (double)fabsf(v.z) + (double)fabsf(v.w);
    }
    sm[threadIdx.x] = s; __syncthreads();
    for (int o = 128; o > 0; o >>= 1) {
        if (threadIdx.x < o) sm[threadIdx.x] += sm[threadIdx.x + o];
        __syncthreads();
    }
    if (threadIdx.x == 0) part[blockIdx.y*64 + blockIdx.x] = sm[0];
}

__global__ void k_finalize_all(const double* __restrict__ part, float* __restrict__ out)
{
    int w = blockIdx.x, tid = threadIdx.x;
    double s = part[w*64 + tid] + part[w*64 + tid + 32];
    for (int o = 16; o; o >>= 1) s += __shfl_xor_sync(0xffffffffu, s, o);
    if (tid == 0) out[w] = fmaxf((float)(s / (double)(CC*CC)), EPSQ);
}

/* ------------------------- ternarize weights (all 4 fused) ----------------- */
__global__ void k_ternarize_all(const float* __restrict__ w0, const float* __restrict__ w1,
                                const float* __restrict__ w2, const float* __restrict__ w3,
                                __nv_bfloat16* __restrict__ wq, const float* __restrict__ mean)
{
    const float* ws[4] = {w0, w1, w2, w3};
    int w = blockIdx.y;
    float inv = 1.0f / mean[w];
    int i = blockIdx.x*blockDim.x + threadIdx.x;
    float4 v = ((const float4*)ws[w])[i];
    float t0 = fminf(fmaxf(rintf(v.x*inv), -1.f), 1.f);
    float t1 = fminf(fmaxf(rintf(v.y*inv), -1.f), 1.f);
    float t2 = fminf(fmaxf(rintf(v.z*inv), -1.f), 1.f);
    float t3 = fminf(fmaxf(rintf(v.w*inv), -1.f), 1.f);
    uint2 u; u.x = pack_bf2(t0,t1); u.y = pack_bf2(t2,t3);
    ((uint2*)(wq + (size_t)w*CC*CC))[i] = u;
}

/* ------------------------- per-row activation quant ------------------------ */
__global__ void k_act_quant(const float* __restrict__ x, __nv_bfloat16* __restrict__ xq,
                            float* __restrict__ ascale)
{
    int row = blockIdx.x;
    int tid = threadIdx.x;
    const float4* xr = (const float4*)(x + (size_t)row*CC);
    float4 v0 = xr[tid*2];
    float4 v1 = xr[tid*2+1];
    float m = fmaxf(fmaxf(fmaxf(fabsf(v0.x), fabsf(v0.y)), fmaxf(fabsf(v0.z), fabsf(v0.w))),
                    fmaxf(fmaxf(fabsf(v1.x), fabsf(v1.y)), fmaxf(fabsf(v1.z), fabsf(v1.w))));
    for (int o = 16; o; o >>= 1) m = fmaxf(m, __shfl_xor_sync(0xffffffffu, m, o));
    __shared__ float sm[4];
    if ((tid & 31) == 0) sm[tid >> 5] = m;
    __syncthreads();
    m = fmaxf(fmaxf(sm[0], sm[1]), fmaxf(sm[2], sm[3]));
    float cm = fmaxf(m, EPSQ);
    float s  = 127.0f / cm;
    float q0 = fminf(fmaxf(rintf(v0.x*s), -128.f), 127.f);
    float q1 = fminf(fmaxf(rintf(v0.y*s), -128.f), 127.f);
    float q2 = fminf(fmaxf(rintf(v0.z*s), -128.f), 127.f);
    float q3 = fminf(fmaxf(rintf(v0.w*s), -128.f), 127.f);
    float q4 = fminf(fmaxf(rintf(v1.x*s), -128.f), 127.f);
    float q5 = fminf(fmaxf(rintf(v1.y*s), -128.f), 127.f);
    float q6 = fminf(fmaxf(rintf(v1.z*s), -128.f), 127.f);
    float q7 = fminf(fmaxf(rintf(v1.w*s), -128.f), 127.f);
    uint4 u;
    u.x = pack_bf2(q0,q1); u.y = pack_bf2(q2,q3);
    u.z = pack_bf2(q4,q5); u.w = pack_bf2(q6,q7);
    *(uint4*)(xq + (size_t)row*CC + tid*8) = u;
    if (tid == 0) ascale[row] = cm * (1.0f/127.0f);
}

/* ------------------------- bf16 tensor-core GEMM --------------------------- */
/* split==0: Cout=f0 gets float (+bias). split==1: writes hi/lo bf16 planes.  */
#define GBM 128
#define GBN 128
#define GBK 64
#define GSTR 72
#define STAGE_ELEMS (128*GSTR)

__global__ __launch_bounds__(256) void k_gemm(
    const __nv_bfloat16* __restrict__ A, const __nv_bfloat16* __restrict__ Bw,
    float* __restrict__ f0,
    __nv_bfloat16* __restrict__ hi0, __nv_bfloat16* __restrict__ lo0,
    __nv_bfloat16* __restrict__ hi1, __nv_bfloat16* __restrict__ lo1,
    __nv_bfloat16* __restrict__ hi2, __nv_bfloat16* __restrict__ lo2,
    const float* __restrict__ ascale, const float* __restrict__ wmean,
    const float* __restrict__ bias, int split)
{
    extern __shared__ __nv_bfloat16 smem[];
    __nv_bfloat16* sA = smem;
    __nv_bfloat16* sB = smem + 2*STAGE_ELEMS;

    const int tid  = threadIdx.x;
    const int m0   = blockIdx.y*GBM;
    const int n0g  = blockIdx.x*GBN;
    const int which= n0g >> 10;
    const int n0   = n0g & 1023;
    __nv_bfloat16* HI = (which == 0) ? hi0 : (which == 1) ? hi1 : hi2;
    __nv_bfloat16* LO = (which == 0) ? lo0 : (which == 1) ? lo1 : lo2;

    const int wid  = tid >> 5, lane = tid & 31;
    const int wm_  = wid & 3, wn_ = wid >> 2;
    const int g    = lane >> 2, t = lane & 3;

    const uint32_t sAu = (uint32_t)__cvta_generic_to_shared(sA);
    const uint32_t sBu = (uint32_t)__cvta_generic_to_shared(sB);

    const int aRow = lane & 15;
    const int aCol = (lane >> 4) << 3;
    const int bRow = (lane & 7) + ((lane & 16) ? 8 : 0);
    const int bCol = (lane & 8) ? 8 : 0;

    const int ldR = tid >> 3;
    const int ldC = (tid & 7) * 8;

    float acc[2][8][4];
    #pragma unroll
    for (int mi=0;mi<2;mi++)
        #pragma unroll
        for (int nj=0;nj<8;nj++)
            #pragma unroll
            for (int q=0;q<4;q++) acc[mi][nj][q] = 0.f;

    {
        #pragma unroll
        for (int i=0;i<4;i++) {
            int r = ldR + i*32;
            cp16(sAu + (uint32_t)((r*GSTR + ldC)*2),
                 A  + (size_t)(m0 + r)*CC + ldC);
            cp16(sBu + (uint32_t)((r*GSTR + ldC)*2),
                 Bw + (size_t)(n0g + r)*CC + ldC);
        }
        cp_commit();
    }

    const int NT = CC / GBK;
    for (int kt = 0; kt < NT; kt++) {
        asm volatile("cp.async.wait_group 0;\n");
        __syncthreads();
        const int s  = kt & 1;
        const int sn = s ^ 1;
        if (kt + 1 < NT) {
            int kb = (kt+1)*GBK;
            #pragma unroll
            for (int i=0;i<4;i++) {
                int r = ldR + i*32;
                cp16(sAu + (uint32_t)((sn*STAGE_ELEMS + r*GSTR + ldC)*2),
                     A  + (size_t)(m0 + r)*CC + kb + ldC);
                cp16(sBu + (uint32_t)((sn*STAGE_ELEMS + r*GSTR + ldC)*2),
                     Bw + (size_t)(n0g + r)*CC + kb + ldC);
            }
            cp_commit();
        }
        const uint32_t aBase = sAu + (uint32_t)(s*STAGE_ELEMS*2);
        const uint32_t bBase = sBu + (uint32_t)(s*STAGE_ELEMS*2);
        #pragma unroll
        for (int kk = 0; kk < 4; kk++) {
            const int k0 = kk*16;
            uint32_t af[2][4], bf[8][2];
            #pragma unroll
            for (int mi=0;mi<2;mi++) {
                int rb = wm_*32 + mi*16;
                ldsm4(af[mi][0], af[mi][1], af[mi][2], af[mi][3],
                      aBase + (uint32_t)((((rb + aRow)*GSTR) + k0 + aCol)*2));
            }
            #pragma unroll
            for (int p=0;p<4;p++) {
                int nb0 = wn_*64 + p*16;
                uint32_t r0,r1,r2,r3;
                ldsm4(r0, r1, r2, r3,
                      bBase + (uint32_t)((((nb0 + bRow)*GSTR) + k0 + bCol)*2));
                bf[2*p][0] = r0; bf[2*p][1] = r1;
                bf[2*p+1][0] = r2; bf[2*p+1][1] = r3;
            }
            #pragma unroll
            for (int mi=0;mi<2;mi++)
                #pragma unroll
                for (int nj=0;nj<8;nj++)
                    mma16816(acc[mi][nj], af[mi], bf[nj]);
        }
        __syncthreads();
    }

    const float wm = wmean[which];
    #pragma unroll
    for (int mi=0;mi<2;mi++) {
        int r0 = m0 + wm_*32 + mi*16 + g;
        float sc0 = ascale[r0]  * wm;
        float sc1 = ascale[r0+8]* wm;
        #pragma unroll
        for (int nj=0;nj<8;nj++) {
            int cidx = n0 + wn_*64 + nj*8 + 2*t;
            float v00 = acc[mi][nj][0]*sc0, v01 = acc[mi][nj][1]*sc0;
            float v10 = acc[mi][nj][2]*sc1, v11 = acc[mi][nj][3]*sc1;
            if (split) {
                float h00 = __bfloat162float(__float2bfloat16(v00));
                float h01 = __bfloat162float(__float2bfloat16(v01));
                float h10 = __bfloat162float(__float2bfloat16(v10));
                float h11 = __bfloat162float(__float2bfloat16(v11));
                *(uint32_t*)&HI[(size_t)r0*CC     + cidx] = pack_bf2(v00, v01);
                *(uint32_t*)&LO[(size_t)r0*CC     + cidx] = pack_bf2(v00-h00, v01-h01);
                *(uint32_t*)&HI[(size_t)(r0+8)*CC + cidx] = pack_bf2(v10, v11);
                *(uint32_t*)&LO[(size_t)(r0+8)*CC + cidx] = pack_bf2(v10-h10, v11-h11);
            } else {
                float b0 = bias ? bias[cidx]   : 0.f;
                float b1 = bias ? bias[cidx+1] : 0.f;
                f0[(size_t)r0*CC     + cidx  ] = v00 + b0;
                f0[(size_t)r0*CC     + cidx+1] = v01 + b1;
                f0[(size_t)(r0+8)*CC + cidx  ] = v10 + b0;
                f0[(size_t)(r0+8)*CC + cidx+1] = v11 + b1;
            }
        }
    }
}

/* ------------------------- bf16 hi/lo flash attention ---------------------- */
/* grid (qt,h,b); 128 threads = 4 warps, warp w owns query rows w*16..w*16+15 */
/* All operands pre-split into bf16 hi/lo planes; inner loop = ldmatrix+mma.  */
#define AS 72                     /* bf16 row stride */
#define APLANE (64*AS)            /* elems per plane */
#define PBYTES (APLANE*2)         /* bytes per plane: 9216 */
#define ATTN_SMEM (12*PBYTES)     /* 110592 */

__global__ __launch_bounds__(128) void k_attn_bf(
    const __nv_bfloat16* __restrict__ Qh, const __nv_bfloat16* __restrict__ Ql,
    const __nv_bfloat16* __restrict__ Kh, const __nv_bfloat16* __restrict__ Kl,
    const __nv_bfloat16* __restrict__ Vh, const __nv_bfloat16* __restrict__ Vl,
    float* __restrict__ Y)
{
    extern __shared__ __nv_bfloat16 bsm[];
    __nv_bfloat16* sPh = bsm + 10*APLANE;
    __nv_bfloat16* sPl = bsm + 11*APLANE;

    const uint32_t u0  = (uint32_t)__cvta_generic_to_shared(bsm);
    const uint32_t uKh = u0;                 /* [2] planes */
    const uint32_t uKl = u0 + 2*PBYTES;
    const uint32_t uVh = u0 + 4*PBYTES;
    const uint32_t uVl = u0 + 6*PBYTES;
    const uint32_t uQh = u0 + 8*PBYTES;
    const uint32_t uQl = u0 + 9*PBYTES;
    const uint32_t uPh = u0 + 10*PBYTES;
    const uint32_t uPl = u0 + 11*PBYTES;

    const int tid = threadIdx.x;
    const int w   = tid >> 5, lane = tid & 31;
    const int g   = lane >> 2, t = lane & 3;
    const int qt  = blockIdx.x, h = blockIdx.y, b = blockIdx.z;
    const int nchunk = qt + 1;
    const size_t qrow0 = (size_t)b*TT + qt*64;
    const size_t krow0 = (size_t)b*TT;
    const int col0 = h*HD;

    /* ldmatrix lane addressing */
    const int aRow  = lane & 15;
    const int aColB = (lane >> 4) * 16;                      /* bytes */
    const int bRow  = (lane & 7) + ((lane & 16) ? 8 : 0);
    const int bColB = (lane & 8) ? 16 : 0;                   /* bytes */

    /* cooperative plane load: 64 rows x 128B; 4 cp16/thread/plane */
    const int lrow = tid >> 3;            /* 0..15, +16 per pass */
    const int lcolB = (tid & 7) * 16;

    #define LD_PLANE(sbase, gptr, grow0)                                        \
        do { _Pragma("unroll")                                                  \
            for (int p_ = 0; p_ < 4; p_++) {                                    \
                int r_ = lrow + p_*16;                                          \
                cp16((sbase) + (uint32_t)(r_*(AS*2) + lcolB),                   \
                     (const char*)(gptr) + (((grow0) + r_)*CC + col0)*2 + lcolB);\
            }                                                                   \
        } while (0)

    /* prefetch chunk 0 (K/V planes) + Q planes */
    LD_PLANE(uKh, Kh, krow0);
    LD_PLANE(uKl, Kl, krow0);
    LD_PLANE(uVh, Vh, krow0);
    LD_PLANE(uVl, Vl, krow0);
    LD_PLANE(uQh, Qh, qrow0);
    LD_PLANE(uQl, Ql, qrow0);
    cp_commit();
    asm volatile("cp.async.wait_group 0;\n");
    __syncthreads();

    /* register-resident Q fragments (hi/lo), 4 k-steps of d */
    uint32_t qhf[4][4], qlf[4][4];
    {
        const int ra = w*16;
        #pragma unroll
        for (int ks=0;ks<4;ks++) {
            uint32_t ad = (uint32_t)(((ra + aRow)*AS)*2 + ks*32 + aColB);
            ldsm4(qhf[ks][0], qhf[ks][1], qhf[ks][2], qhf[ks][3], uQh + ad);
            ldsm4(qlf[ks][0], qlf[ks][1], qlf[ks][2], qlf[ks][3], uQl + ad);
        }
    }

    float oacc[8][4];
    #pragma unroll
    for (int nt=0;nt<8;nt++)
        #pragma unroll
        for (int q=0;q<4;q++) oacc[nt][q] = 0.f;
    float mg = -INFINITY, mg8 = -INFINITY, lg = 0.f, lg8 = 0.f;

    for (int kc = 0; kc < nchunk; kc++) {
        const int buf = kc & 1;
        if (kc + 1 < nchunk) {
            const uint32_t nb = (uint32_t)(((kc+1) & 1) * PBYTES);
            const size_t nr = krow0 + (kc+1)*64;
            LD_PLANE(uKh + nb, Kh, nr);
            LD_PLANE(uKl + nb, Kl, nr);
            LD_PLANE(uVh + nb, Vh, nr);
            LD_PLANE(uVl + nb, Vl, nr);
            cp_commit();
            asm volatile("cp.async.wait_group 1;\n");
        } else {
            asm volatile("cp.async.wait_group 0;\n");
        }
        __syncthreads();

        const uint32_t kb_h = uKh + buf*PBYTES;
        const uint32_t kb_l = uKl + buf*PBYTES;
        const uint32_t vb_h = uVh + buf*PBYTES;
        const uint32_t vb_l = uVl + buf*PBYTES;

        /* S = Q K^T : A=Q[q][d], B=K (rows=key, contiguous d) */
        float sacc[8][4];
        #pragma unroll
        for (int nt=0;nt<8;nt++)
            #pragma unroll
            for (int q=0;q<4;q++) sacc[nt][q] = 0.f;
        #pragma unroll
        for (int ks=0;ks<4;ks++) {
            #pragma unroll
            for (int p=0;p<4;p++) {
                uint32_t ad = (uint32_t)(((p*16 + bRow)*AS)*2 + ks*32 + bColB);
                uint32_t bh[4], bl[4];
                ldsm4(bh[0], bh[1], bh[2], bh[3], kb_h + ad);
                ldsm4(bl[0], bl[1], bl[2], bl[3], kb_l + ad);
                mma16816(sacc[2*p  ], qhf[ks], bh    );
                mma16816(sacc[2*p  ], qhf[ks], bl    );
                mma16816(sacc[2*p  ], qlf[ks], bh    );
                mma16816(sacc[2*p+1], qhf[ks], bh + 2);
                mma16816(sacc[2*p+1], qhf[ks], bl + 2);
                mma16816(sacc[2*p+1], qlf[ks], bh + 2);
            }
        }

        /* scale + causal mask (diagonal chunk only) */
        const bool diag = (kc == qt);
        const int qlr  = w*16 + g;
        const int qlr8 = qlr + 8;
        #pragma unroll
        for (int nt=0;nt<8;nt++) {
            int kl0 = nt*8 + 2*t, kl1 = kl0 + 1;
            sacc[nt][0] = (diag && kl0 > qlr ) ? -INFINITY : sacc[nt][0]*0.125f;
            sacc[nt][1] = (diag && kl1 > qlr ) ? -INFINITY : sacc[nt][1]*0.125f;
            sacc[nt][2] = (diag && kl0 > qlr8) ? -INFINITY : sacc[nt][2]*0.125f;
            sacc[nt][3] = (diag && kl1 > qlr8) ? -INFINITY : sacc[nt][3]*0.125f;
        }

        /* online softmax */
        float cm = -INFINITY, cm8 = -INFINITY;
        #pragma unroll
        for (int nt=0;nt<8;nt++) {
            cm  = fmaxf(cm,  fmaxf(sacc[nt][0], sacc[nt][1]));
            cm8 = fmaxf(cm8, fmaxf(sacc[nt][2], sacc[nt][3]));
        }
        #pragma unroll
        for (int o=1;o<4;o<<=1) {
            cm  = fmaxf(cm,  __shfl_xor_sync(0xffffffffu, cm,  o));
            cm8 = fmaxf(cm8, __shfl_xor_sync(0xffffffffu, cm8, o));
        }
        float nm  = fmaxf(mg,  cm);
        float nm8 = fmaxf(mg8, cm8);
        float sc  = __expf(mg  - nm);
        float sc8 = __expf(mg8 - nm8);
        mg = nm; mg8 = nm8;

        float rs = 0.f, rs8 = 0.f;
        const int pr = w*16 + g;
        #pragma unroll
        for (int nt=0;nt<8;nt++) {
            float e0 = __expf(sacc[nt][0] - nm);
            float e1 = __expf(sacc[nt][1] - nm);
            float e2 = __expf(sacc[nt][2] - nm8);
            float e3 = __expf(sacc[nt][3] - nm8);
            rs  += e0 + e1;  rs8 += e2 + e3;
            float h0 = __bfloat162float(__float2bfloat16(e0));
            float h1 = __bfloat162float(__float2bfloat16(e1));
            float h2 = __bfloat162float(__float2bfloat16(e2));
            float h3 = __bfloat162float(__float2bfloat16(e3));
            *(uint32_t*)&sPh[(pr  )*AS + nt*8 + 2*t] = pack_bf2(e0, e1);
            *(uint32_t*)&sPl[(pr  )*AS + nt*8 + 2*t] = pack_bf2(e0-h0, e1-h1);
            *(uint32_t*)&sPh[(pr+8)*AS + nt*8 + 2*t] = pack_bf2(e2, e3);
            *(uint32_t*)&sPl[(pr+8)*AS + nt*8 + 2*t] = pack_bf2(e2-h2, e3-h3);
        }
        #pragma unroll
        for (int o=1;o<4;o<<=1) {
            rs  += __shfl_xor_sync(0xffffffffu, rs,  o);
            rs8 += __shfl_xor_sync(0xffffffffu, rs8, o);
        }
        lg  = lg *sc  + rs;
        lg8 = lg8*sc8 + rs8;

        #pragma unroll
        for (int nt=0;nt<8;nt++) {
            oacc[nt][0] *= sc;  oacc[nt][1] *= sc;
            oacc[nt][2] *= sc8; oacc[nt][3] *= sc8;
        }
        __syncwarp();     /* P visible within warp (each warp reads own rows) */

        /* O += P V : A=P[q][key] (warp's rows), B=V^T via ldmatrix.trans */
        #pragma unroll
        for (int ks=0;ks<4;ks++) {            /* key k-steps of 16 */
            uint32_t pa[4], pb[4];
            uint32_t pad = (uint32_t)(((w*16 + aRow)*AS)*2 + ks*32 + aColB);
            ldsm4(pa[0], pa[1], pa[2], pa[3], uPh + pad);
            ldsm4(pb[0], pb[1], pb[2], pb[3], uPl + pad);
            #pragma unroll
            for (int p=0;p<4;p++) {           /* d n-tiles of 16 */
                uint32_t vd = (uint32_t)(((ks*16 + aRow)*AS)*2 + p*32 + aColB);
                uint32_t vh[4], vl[4];
                ldsm4t(vh[0], vh[1], vh[2], vh[3], vb_h + vd);
                ldsm4t(vl[0], vl[1], vl[2], vl[3], vb_l + vd);
                mma16816(oacc[2*p  ], pa, vh    );
                mma16816(oacc[2*p  ], pa, vl    );
                mma16816(oacc[2*p  ], pb, vh    );
                mma16816(oacc[2*p+1], pa, vh + 2);
                mma16816(oacc[2*p+1], pa, vl + 2);
                mma16816(oacc[2*p+1], pb, vh + 2);
            }
        }
        __syncthreads();    /* all V reads done before next chunk overwrite */
    }

    float inv  = 1.0f/lg;
    float inv8 = 1.0f/lg8;
    const size_t r0 = qrow0 + w*16 + g;
    #pragma unroll
    for (int nt=0;nt<8;nt++) {
        float2 o0; o0.x = oacc[nt][0]*inv;  o0.y = oacc[nt][1]*inv;
        float2 o1; o1.x = oacc[nt][2]*inv8; o1.y = oacc[nt][3]*inv8;
        *(float2*)&Y[(r0    )*CC + col0 + nt*8 + 2*t] = o0;
        *(float2*)&Y[(r0 + 8)*CC + col0 + nt*8 + 2*t] = o1;
    }
}

/* ------------------------- launch --------------------------------------- */
extern "C" void kernel_launch(void* const* d_in, const int* in_sizes, int n_in,
                              void* d_out, int out_size)
{
    const float* x  = (const float*)d_in[0];
    const float* W0 = (const float*)d_in[1];
    const float* W1 = (const float*)d_in[2];
    const float* W2 = (const float*)d_in[3];
    const float* W3 = (const float*)d_in[4];
    const float* bp = (const float*)d_in[5];

    float* wmean;   cudaGetSymbolAddress((void**)&wmean,  g_wmean);
    double* part;   cudaGetSymbolAddress((void**)&part,   g_partial);
    __nv_bfloat16* wq;  cudaGetSymbolAddress((void**)&wq,  g_wq);
    __nv_bfloat16* xq;  cudaGetSymbolAddress((void**)&xq,  g_xq);
    float* ascale;  cudaGetSymbolAddress((void**)&ascale, g_ascale);
    __nv_bfloat16* qhi; cudaGetSymbolAddress((void**)&qhi, g_qhi);
    __nv_bfloat16* qlo; cudaGetSymbolAddress((void**)&qlo, g_qlo);
    __nv_bfloat16* khi; cudaGetSymbolAddress((void**)&khi, g_khi);
    __nv_bfloat16* klo; cudaGetSymbolAddress((void**)&klo, g_klo);
    __nv_bfloat16* vhi; cudaGetSymbolAddress((void**)&vhi, g_vhi);
    __nv_bfloat16* vlo; cudaGetSymbolAddress((void**)&vlo, g_vlo);
    float* yb;      cudaGetSymbolAddress((void**)&yb,     g_yb);
    __nv_bfloat16* yq;  cudaGetSymbolAddress((void**)&yq,  g_yq);
    float* yscale;  cudaGetSymbolAddress((void**)&yscale, g_yscale);

    const int GEMM_SMEM = 4*STAGE_ELEMS*(int)sizeof(__nv_bfloat16);   /* 73728 */
    cudaFuncSetAttribute(k_gemm,    cudaFuncAttributeMaxDynamicSharedMemorySize, GEMM_SMEM);
    cudaFuncSetAttribute(k_attn_bf, cudaFuncAttributeMaxDynamicSharedMemorySize, ATTN_SMEM);

    k_absmean_all  <<<dim3(64,4), 256>>>(W0, W1, W2, W3, part);
    k_finalize_all <<<4, 32>>>(part, wmean);
    k_ternarize_all<<<dim3(1024,4), 256>>>(W0, W1, W2, W3, wq, wmean);

    k_act_quant<<<MM, 128>>>(x, xq, ascale);

    /* fused QKV GEMM: N = 3072; outputs split to bf16 hi/lo planes */
    dim3 gqkv(3*CC/GBN, MM/GBM);   /* (24, 128) */
    k_gemm<<<gqkv, 256, GEMM_SMEM>>>(xq, wq, nullptr,
                                     qhi, qlo, khi, klo, vhi, vlo,
                                     ascale, wmean, nullptr, 1);

    dim3 agrid(TT/64, HH, BB);     /* (4, 16, 64) */
    k_attn_bf<<<agrid, 128, ATTN_SMEM>>>(qhi, qlo, khi, klo, vhi, vlo, yb);

    k_act_quant<<<MM, 128>>>(yb, yq, yscale);

    /* projection GEMM: N = 1024, fp32 out + bias */
    dim3 gproj(CC/GBN, MM/GBM);    /* (8, 128) */
    k_gemm<<<gproj, 256, GEMM_SMEM>>>(yq, wq + 3*(size_t)CC*CC, (float*)d_out,
                                      nullptr, nullptr, nullptr, nullptr, nullptr, nullptr,
                                      yscale, wmean + 3, bp, 0);
}